// round 13
// baseline (speedup 1.0000x reference)
#include <cuda_runtime.h>
#include <cuda_bf16.h>
#include <math.h>
#include <stdint.h>

// Problem constants
#define BT   16          // B*T
#define E    768
#define NXD  32
#define NYD  32
#define NP   1024        // NX*NY
#define TOK  (BT*NP)     // 16384 tokens
#define KM   12          // kept y modes
#define J24  24          // kept x modes (kx = 5..28)
#define KX0  5
#define NMODE 288        // 24*12
#define HID  3072
#define TWO_PI_32 0.19634954084936207f

// ---------------- scratch (static device allocations; no cudaMalloc) ----------------
__device__ float g_h [TOK*E];          // LN1 output
__device__ float g_U [BT*NXD*KM*E];    // fwd y-DFT real
__device__ float g_V [BT*NXD*KM*E];    // fwd y-DFT imag
__device__ float g_fr[BT*NMODE*E];
__device__ float g_fi[BT*NMODE*E];
__device__ float g_sr[BT*NMODE*E];
__device__ float g_si[BT*NMODE*E];
__device__ float g_r1[TOK*E];          // spat + h + input  (res2)
__device__ float g_y [TOK*E];          // LN2 output
__device__ float g_mid[(size_t)TOK*HID]; // gelu(y@mw1+mb1)

__device__ __forceinline__ float gelu_f(float x) {
    return 0.5f * x * (1.0f + erff(x * 0.7071067811865475f));
}
__device__ __forceinline__ float softshrink_f(float x) {
    return x > 0.01f ? x - 0.01f : (x < -0.01f ? x + 0.01f : 0.0f);
}
__device__ __forceinline__ uint32_t packbf2(float lo, float hi) {
    __nv_bfloat162 p = __floats2bfloat162_rn(lo, hi);   // .x = lo (low 16 bits)
    return *reinterpret_cast<uint32_t*>(&p);
}

// ---------------- block-wide (768-thread) LN stats: sum & sumsq of one value/thread ----
// Uses shared red/red2 (24 warps) + mS/rS broadcast. Two __syncthreads per call.
__device__ __forceinline__ void ln_stats_768(float v, float* red, float* red2,
                                             float& mS_sh, float& rS_sh,
                                             float& mOut, float& rOut) {
    int t = threadIdx.x;
    float s = v, s2 = v * v;
    #pragma unroll
    for (int o = 16; o > 0; o >>= 1) {
        s  += __shfl_down_sync(0xffffffffu, s,  o);
        s2 += __shfl_down_sync(0xffffffffu, s2, o);
    }
    if ((t & 31) == 0) { red[t >> 5] = s; red2[t >> 5] = s2; }
    __syncthreads();
    if (t == 0) {
        float ts = 0.f, ts2 = 0.f;
        #pragma unroll
        for (int i = 0; i < 24; i++) { ts += red[i]; ts2 += red2[i]; }
        float m = ts * (1.0f / 768.0f);
        float var = ts2 * (1.0f / 768.0f) - m * m;
        mS_sh = m; rS_sh = rsqrtf(var + 1e-5f);
    }
    __syncthreads();
    mOut = mS_sh; rOut = rS_sh;
}

// ---------------- FUSED: LN1 + forward y-DFT ----------------
// one block per (bt,x) = 512 blocks, 768 threads (e)
__global__ void ln1_fwdy_kernel(const float* __restrict__ inp,
                                const float* __restrict__ g,
                                const float* __restrict__ b) {
    __shared__ float C[32], S[32];
    __shared__ float red[24], red2[24];
    __shared__ float mS, rS;
    int e = threadIdx.x;
    if (e < 32) {
        float a = e * TWO_PI_32;
        C[e] = cosf(a); S[e] = sinf(a);
    }
    int bx = blockIdx.x;                    // bt*32 + x
    float U[KM], V[KM];
    #pragma unroll
    for (int k = 0; k < KM; k++) { U[k] = 0.f; V[k] = 0.f; }
    float ge = g[e], be = b[e];
    const float* ip = inp + (size_t)bx * 32 * E + e;
    float* hp = g_h + (size_t)bx * 32 * E + e;

    for (int y = 0; y < 32; y++) {
        float v = ip[(size_t)y * E];
        float m, r;
        ln_stats_768(v, red, red2, mS, rS, m, r);   // C/S ready: a sync precedes use
        float h = (v - m) * r * ge + be;
        hp[(size_t)y * E] = h;
        #pragma unroll
        for (int ky = 0; ky < KM; ky++) {
            int mm = (y * ky) & 31;
            U[ky] += h * C[mm];
            V[ky] -= h * S[mm];
        }
    }
    float* up = g_U + (size_t)bx * KM * E + e;
    float* vp = g_V + (size_t)bx * KM * E + e;
    #pragma unroll
    for (int ky = 0; ky < KM; ky++) {
        up[(size_t)ky * E] = U[ky];
        vp[(size_t)ky * E] = V[ky];
    }
}

// ---------------- forward DFT stage 2 (over x) ----------------
__global__ void fwd_x_kernel() {
    __shared__ float C[32], S[32];
    if (threadIdx.x < 32) {
        float a = threadIdx.x * TWO_PI_32;
        C[threadIdx.x] = cosf(a); S[threadIdx.x] = sinf(a);
    }
    __syncthreads();
    int e  = threadIdx.x;
    int ky = blockIdx.x % KM;
    int bt = blockIdx.x / KM;
    int j0 = blockIdx.y * 12;
    float fr[12], fi[12];
    #pragma unroll
    for (int j = 0; j < 12; j++) { fr[j] = 0.f; fi[j] = 0.f; }
    const float* up = g_U + ((size_t)(bt * 32) * KM + ky) * E + e;
    const float* vp = g_V + ((size_t)(bt * 32) * KM + ky) * E + e;
    for (int x = 0; x < 32; x++) {
        float u = up[(size_t)x * KM * E];
        float v = vp[(size_t)x * KM * E];
        #pragma unroll
        for (int jj = 0; jj < 12; jj++) {
            int kx = j0 + jj + KX0;
            int m = (kx * x) & 31;
            float c = C[m], s = S[m];
            fr[jj] += u * c + v * s;
            fi[jj] += v * c - u * s;
        }
    }
    const float sc = 1.0f / 32.0f;
    #pragma unroll
    for (int jj = 0; jj < 12; jj++) {
        size_t idx = ((size_t)bt * NMODE + (size_t)(j0 + jj) * KM + ky) * E + e;
        g_fr[idx] = fr[jj] * sc;
        g_fi[idx] = fi[jj] * sc;
    }
}

// ---------------- block-diagonal complex MLP (4 mode-positions per block) ----------------
#define MPB 4
__global__ void bmlp_kernel(const float* __restrict__ w1, const float* __restrict__ b1,
                            const float* __restrict__ w2, const float* __restrict__ b2) {
    __shared__ float sfr[MPB][768], sfi[MPB][768];
    int t = threadIdx.x;
    size_t base = (size_t)blockIdx.x * MPB * E;
    #pragma unroll
    for (int m = 0; m < MPB; m++) {
        sfr[m][t] = g_fr[base + (size_t)m * E + t];
        sfi[m][t] = g_fi[base + (size_t)m * E + t];
    }
    __syncthreads();
    int n = t >> 6;

    const float* w0p = w1 + ((size_t)n * 64) * 64 + (t & 63);
    const float* w1p = w1 + ((size_t)(12 + n) * 64) * 64 + (t & 63);
    float ar[MPB], ai[MPB];
    float bre = b1[t], bim = b1[768 + t];
    #pragma unroll
    for (int m = 0; m < MPB; m++) { ar[m] = bre; ai[m] = bim; }
    #pragma unroll 8
    for (int i = 0; i < 64; i++) {
        float a  = w0p[(size_t)i * 64];
        float bb = w1p[(size_t)i * 64];
        #pragma unroll
        for (int m = 0; m < MPB; m++) {
            float fr = sfr[m][n * 64 + i], fi = sfi[m][n * 64 + i];
            ar[m] += fr * a - fi * bb;
            ai[m] += fi * a + fr * bb;
        }
    }
    __syncthreads();
    #pragma unroll
    for (int m = 0; m < MPB; m++) {
        sfr[m][t] = gelu_f(ar[m]);
        sfi[m][t] = gelu_f(ai[m]);
    }
    __syncthreads();

    const float* u0p = w2 + ((size_t)n * 64) * 64 + (t & 63);
    const float* u1p = w2 + ((size_t)(12 + n) * 64) * 64 + (t & 63);
    float cr[MPB], ci[MPB];
    float cre = b2[t], cim = b2[768 + t];
    #pragma unroll
    for (int m = 0; m < MPB; m++) { cr[m] = cre; ci[m] = cim; }
    #pragma unroll 8
    for (int i = 0; i < 64; i++) {
        float a  = u0p[(size_t)i * 64];
        float bb = u1p[(size_t)i * 64];
        #pragma unroll
        for (int m = 0; m < MPB; m++) {
            float orr = sfr[m][n * 64 + i], oii = sfi[m][n * 64 + i];
            cr[m] += orr * a - oii * bb;
            ci[m] += oii * a + orr * bb;
        }
    }
    #pragma unroll
    for (int m = 0; m < MPB; m++) {
        g_sr[base + (size_t)m * E + t] = softshrink_f(cr[m]);
        g_si[base + (size_t)m * E + t] = softshrink_f(ci[m]);
    }
}

// ---------------- FUSED: inverse x-iDFT + inverse y-iDFT + residuals + LN2 ----------------
// one block per (bt,x) = 512 blocks, 768 threads (e)
__global__ void inv_fused_kernel(const float* __restrict__ inp,
                                 const float* __restrict__ g2,
                                 const float* __restrict__ b2) {
    __shared__ float C[32], S[32];
    __shared__ float red[24], red2[24];
    __shared__ float mS, rS;
    int e = threadIdx.x;
    if (e < 32) {
        float a = e * TWO_PI_32;
        C[e] = cosf(a); S[e] = sinf(a);
    }
    __syncthreads();
    int bx = blockIdx.x;
    int x  = bx & 31;
    int bt = bx >> 5;

    // stage 1: P/Q accumulation over kx (24 j values), all 12 ky in registers
    float P[KM], Q[KM];
    #pragma unroll
    for (int k = 0; k < KM; k++) { P[k] = 0.f; Q[k] = 0.f; }
    const float* srp = g_sr + (size_t)bt * NMODE * E + e;
    const float* sip = g_si + (size_t)bt * NMODE * E + e;
    for (int j = 0; j < J24; j++) {
        int m = ((j + KX0) * x) & 31;
        float c = C[m], s = S[m];
        #pragma unroll
        for (int ky = 0; ky < KM; ky++) {
            size_t off = (size_t)(j * KM + ky) * E;
            float sr = srp[off];
            float si = sip[off];
            P[ky] += sr * c - si * s;
            Q[ky] += sr * s + si * c;
        }
    }
    #pragma unroll
    for (int ky = 0; ky < KM; ky++) {
        float wgt = (ky == 0 ? 1.0f : 2.0f) * (1.0f / 32.0f);
        P[ky] *= wgt;
        Q[ky] *= wgt;
    }

    // stage 2: y-iDFT + residual adds + LN2, row by row
    const float* hp = g_h + (size_t)bx * 32 * E + e;
    const float* ip = inp + (size_t)bx * 32 * E + e;
    float* r1p = g_r1 + (size_t)bx * 32 * E + e;
    float* yp  = g_y  + (size_t)bx * 32 * E + e;
    float ge = g2[e], be = b2[e];

    for (int y = 0; y < 32; y++) {
        float acc = 0.f;
        #pragma unroll
        for (int ky = 0; ky < KM; ky++) {
            int mm = (ky * y) & 31;
            acc += P[ky] * C[mm] - Q[ky] * S[mm];
        }
        float r1 = acc + hp[(size_t)y * E] + ip[(size_t)y * E];
        r1p[(size_t)y * E] = r1;
        float m, r;
        ln_stats_768(r1, red, red2, mS, rS, m, r);
        yp[(size_t)y * E] = (r1 - m) * r * ge + be;
    }
}

// ======================================================================
//  BF16 tensor-core GEMM (PROVEN in R12): 128x128 block tile, 8 warps,
//  warp tile 64x32, m16n8k16, BK=16, double-buffered packed-bf16x2 SMEM.
// ======================================================================
#define BM 128
#define BN 128
#define BK 16
#define ASP 12      // As word stride per row
#define BSP 132     // Bp word stride per k-pair row

__device__ __forceinline__ void mma_bf16(float* c, const uint32_t* a, const uint32_t* b) {
    asm volatile(
        "mma.sync.aligned.m16n8k16.row.col.f32.bf16.bf16.f32 "
        "{%0,%1,%2,%3}, {%4,%5,%6,%7}, {%8,%9}, {%0,%1,%2,%3};\n"
        : "+f"(c[0]), "+f"(c[1]), "+f"(c[2]), "+f"(c[3])
        : "r"(a[0]), "r"(a[1]), "r"(a[2]), "r"(a[3]), "r"(b[0]), "r"(b[1]));
}

template<int N_, bool GELU, bool RESID>
__device__ __forceinline__ void gemm_bf_core(const float* __restrict__ A,
                                             const float* __restrict__ Bm,
                                             const float* __restrict__ bias,
                                             const float* __restrict__ res,
                                             float* __restrict__ Cout, int K) {
    __shared__ uint32_t Asp[2][BM * ASP];
    __shared__ uint32_t Bps[2][8 * BSP];

    int t = threadIdx.x;
    int lane = t & 31, wid = t >> 5;
    int gid = lane >> 2, tig = lane & 3;
    int wm = (wid & 1) * 64;
    int wn = (wid >> 1) * 32;
    int m0 = blockIdx.y * BM, n0 = blockIdx.x * BN;

    float acc[4][4][4];
    #pragma unroll
    for (int i = 0; i < 4; i++)
        #pragma unroll
        for (int j = 0; j < 4; j++)
            #pragma unroll
            for (int k = 0; k < 4; k++) acc[i][j][k] = 0.f;

    int ar = t >> 2;
    int ac = (t & 3) * 4;
    int acw = (t & 3) * 2;
    int bp = t >> 5;
    int bc = (t & 31) * 4;
    const float* Ap0 = A + (size_t)(m0 + ar) * K + ac;
    const float* Ap1 = A + (size_t)(m0 + ar + 64) * K + ac;
    const float* Bp0 = Bm + (size_t)(2 * bp) * N_ + n0 + bc;
    const float* Bp1 = Bp0 + N_;

    int NT = K / BK;

    {
        float4 a0 = *(const float4*)(Ap0);
        float4 a1 = *(const float4*)(Ap1);
        float4 b0 = *(const float4*)(Bp0);
        float4 b1 = *(const float4*)(Bp1);
        uint32_t* As_ = Asp[0]; uint32_t* Bs_ = Bps[0];
        As_[ar * ASP + acw]            = packbf2(a0.x, a0.y);
        As_[ar * ASP + acw + 1]        = packbf2(a0.z, a0.w);
        As_[(ar + 64) * ASP + acw]     = packbf2(a1.x, a1.y);
        As_[(ar + 64) * ASP + acw + 1] = packbf2(a1.z, a1.w);
        Bs_[bp * BSP + bc + 0] = packbf2(b0.x, b1.x);
        Bs_[bp * BSP + bc + 1] = packbf2(b0.y, b1.y);
        Bs_[bp * BSP + bc + 2] = packbf2(b0.z, b1.z);
        Bs_[bp * BSP + bc + 3] = packbf2(b0.w, b1.w);
    }
    __syncthreads();

    for (int kt = 0; kt < NT; kt++) {
        float4 a0, a1, b0, b1;
        bool has = (kt + 1) < NT;
        if (has) {
            int k0 = (kt + 1) * BK;
            a0 = *(const float4*)(Ap0 + k0);
            a1 = *(const float4*)(Ap1 + k0);
            b0 = *(const float4*)(Bp0 + (size_t)k0 * N_);
            b1 = *(const float4*)(Bp1 + (size_t)k0 * N_);
        }

        const uint32_t* Asb = Asp[kt & 1];
        const uint32_t* Bsb = Bps[kt & 1];
        uint32_t af[4][4];
        #pragma unroll
        for (int ma = 0; ma < 4; ma++) {
            int r = wm + ma * 16 + gid;
            af[ma][0] = Asb[r * ASP + tig];
            af[ma][1] = Asb[(r + 8) * ASP + tig];
            af[ma][2] = Asb[r * ASP + tig + 4];
            af[ma][3] = Asb[(r + 8) * ASP + tig + 4];
        }
        uint32_t bf[4][2];
        #pragma unroll
        for (int na = 0; na < 4; na++) {
            int c = wn + na * 8 + gid;
            bf[na][0] = Bsb[tig * BSP + c];
            bf[na][1] = Bsb[(tig + 4) * BSP + c];
        }
        #pragma unroll
        for (int ma = 0; ma < 4; ma++)
            #pragma unroll
            for (int na = 0; na < 4; na++)
                mma_bf16(acc[ma][na], af[ma], bf[na]);

        if (has) {
            uint32_t* As_ = Asp[(kt + 1) & 1];
            uint32_t* Bs_ = Bps[(kt + 1) & 1];
            As_[ar * ASP + acw]            = packbf2(a0.x, a0.y);
            As_[ar * ASP + acw + 1]        = packbf2(a0.z, a0.w);
            As_[(ar + 64) * ASP + acw]     = packbf2(a1.x, a1.y);
            As_[(ar + 64) * ASP + acw + 1] = packbf2(a1.z, a1.w);
            Bs_[bp * BSP + bc + 0] = packbf2(b0.x, b1.x);
            Bs_[bp * BSP + bc + 1] = packbf2(b0.y, b1.y);
            Bs_[bp * BSP + bc + 2] = packbf2(b0.z, b1.z);
            Bs_[bp * BSP + bc + 3] = packbf2(b0.w, b1.w);
        }
        __syncthreads();
    }

    #pragma unroll
    for (int ma = 0; ma < 4; ma++) {
        size_t r = m0 + wm + ma * 16 + gid;
        #pragma unroll
        for (int na = 0; na < 4; na++) {
            int c = n0 + wn + na * 8 + tig * 2;
            float v0 = acc[ma][na][0] + bias[c];
            float v1 = acc[ma][na][1] + bias[c + 1];
            float v2 = acc[ma][na][2] + bias[c];
            float v3 = acc[ma][na][3] + bias[c + 1];
            if (GELU) { v0 = gelu_f(v0); v1 = gelu_f(v1); v2 = gelu_f(v2); v3 = gelu_f(v3); }
            if (RESID) {
                float2 r0 = *(const float2*)(res + r * N_ + c);
                float2 r1 = *(const float2*)(res + (r + 8) * N_ + c);
                v0 += r0.x; v1 += r0.y; v2 += r1.x; v3 += r1.y;
            }
            *(float2*)(Cout + r * N_ + c) = make_float2(v0, v1);
            *(float2*)(Cout + (r + 8) * N_ + c) = make_float2(v2, v3);
        }
    }
}

__global__ __launch_bounds__(256, 2) void gemm1_bf_kernel(const float* __restrict__ mw1,
                                                          const float* __restrict__ mb1) {
    gemm_bf_core<HID, true, false>(g_y, mw1, mb1, nullptr, g_mid, E);
}
__global__ __launch_bounds__(256, 2) void gemm2_bf_kernel(const float* __restrict__ mw2,
                                                          const float* __restrict__ mb2,
                                                          float* __restrict__ out) {
    gemm_bf_core<E, false, true>(g_mid, mw2, mb2, g_r1, out, HID);
}

// ---------------- launch ----------------
extern "C" void kernel_launch(void* const* d_in, const int* in_sizes, int n_in,
                              void* d_out, int out_size) {
    const float* inp  = (const float*)d_in[0];
    const float* w1   = (const float*)d_in[1];
    const float* b1   = (const float*)d_in[2];
    const float* w2   = (const float*)d_in[3];
    const float* b2   = (const float*)d_in[4];
    const float* ln1g = (const float*)d_in[5];
    const float* ln1b = (const float*)d_in[6];
    const float* ln2g = (const float*)d_in[7];
    const float* ln2b = (const float*)d_in[8];
    const float* mw1  = (const float*)d_in[9];
    const float* mb1  = (const float*)d_in[10];
    const float* mw2  = (const float*)d_in[11];
    const float* mb2  = (const float*)d_in[12];
    float* out = (float*)d_out;

    ln1_fwdy_kernel<<<BT * NXD, 768>>>(inp, ln1g, ln1b);
    fwd_x_kernel<<<dim3(BT * KM, 2), 768>>>();
    bmlp_kernel<<<BT * NMODE / MPB, 768>>>(w1, b1, w2, b2);
    inv_fused_kernel<<<BT * NXD, 768>>>(inp, ln2g, ln2b);
    gemm1_bf_kernel<<<dim3(HID / BN, TOK / BM), 256>>>(mw1, mb1);
    gemm2_bf_kernel<<<dim3(E / BN, TOK / BM), 256>>>(mw2, mb2, out);
}

// round 15
// speedup vs baseline: 1.1203x; 1.1203x over previous
#include <cuda_runtime.h>
#include <cuda_bf16.h>
#include <math.h>
#include <stdint.h>

// Problem constants
#define BT   16          // B*T
#define E    768
#define NXD  32
#define NYD  32
#define NP   1024        // NX*NY
#define TOK  (BT*NP)     // 16384 tokens
#define KM   12          // kept y modes
#define J24  24          // kept x modes (kx = 5..28)
#define KX0  5
#define NMODE 288        // 24*12
#define HID  3072
#define TWO_PI_32 0.19634954084936207f

// ---------------- scratch (static device allocations; no cudaMalloc) ----------------
__device__ float g_h [TOK*E];          // LN1 output
__device__ float g_U [BT*NXD*KM*E];    // fwd y-DFT real
__device__ float g_V [BT*NXD*KM*E];    // fwd y-DFT imag
__device__ float g_fr[BT*NMODE*E];
__device__ float g_fi[BT*NMODE*E];
__device__ float g_sr[BT*NMODE*E];
__device__ float g_si[BT*NMODE*E];
__device__ float g_P [BT*NXD*KM*E];    // inv x-iDFT real (pre-weighted)
__device__ float g_Q [BT*NXD*KM*E];
__device__ float g_r1[TOK*E];          // spat + h + input  (res2)
__device__ float g_y [TOK*E];          // LN2 output
__device__ __nv_bfloat16 g_midh[(size_t)TOK*HID]; // gelu(y@mw1+mb1) (bf16)

__device__ __forceinline__ float gelu_f(float x) {
    return 0.5f * x * (1.0f + erff(x * 0.7071067811865475f));
}
__device__ __forceinline__ float softshrink_f(float x) {
    return x > 0.01f ? x - 0.01f : (x < -0.01f ? x + 0.01f : 0.0f);
}
__device__ __forceinline__ uint32_t packbf2(float lo, float hi) {
    __nv_bfloat162 p = __floats2bfloat162_rn(lo, hi);   // .x = lo (low 16 bits)
    return *reinterpret_cast<uint32_t*>(&p);
}

// ---------------- LayerNorm (one block per token, 256 threads, 3 elems/thread) ----------------
__device__ __forceinline__ void ln_row(const float* __restrict__ xr,
                                       const float* __restrict__ g,
                                       const float* __restrict__ b,
                                       float* __restrict__ orow) {
    int t = threadIdx.x;
    float v0 = xr[t], v1 = xr[t + 256], v2 = xr[t + 512];
    float s  = v0 + v1 + v2;
    float s2 = v0*v0 + v1*v1 + v2*v2;
    #pragma unroll
    for (int o = 16; o > 0; o >>= 1) {
        s  += __shfl_down_sync(0xffffffffu, s,  o);
        s2 += __shfl_down_sync(0xffffffffu, s2, o);
    }
    __shared__ float sa[8], sb[8];
    __shared__ float mS, rS;
    if ((t & 31) == 0) { sa[t >> 5] = s; sb[t >> 5] = s2; }
    __syncthreads();
    if (t == 0) {
        float ts = 0.f, ts2 = 0.f;
        #pragma unroll
        for (int i = 0; i < 8; i++) { ts += sa[i]; ts2 += sb[i]; }
        float m = ts * (1.0f / 768.0f);
        float var = ts2 * (1.0f / 768.0f) - m * m;
        mS = m; rS = rsqrtf(var + 1e-5f);
    }
    __syncthreads();
    float m = mS, r = rS;
    orow[t]       = (v0 - m) * r * g[t]       + b[t];
    orow[t + 256] = (v1 - m) * r * g[t + 256] + b[t + 256];
    orow[t + 512] = (v2 - m) * r * g[t + 512] + b[t + 512];
}

__global__ void ln1_kernel(const float* __restrict__ x,
                           const float* __restrict__ g,
                           const float* __restrict__ b) {
    size_t row = blockIdx.x;
    ln_row(x + row * E, g, b, g_h + row * E);
}
__global__ void ln2_kernel(const float* __restrict__ g,
                           const float* __restrict__ b) {
    size_t row = blockIdx.x;
    ln_row(g_r1 + row * E, g, b, g_y + row * E);
}

// ---------------- forward DFT stage 1 (over y) ----------------
__global__ void fwd_y_kernel() {
    __shared__ float C[32], S[32];
    if (threadIdx.x < 32) {
        float a = threadIdx.x * TWO_PI_32;
        C[threadIdx.x] = cosf(a); S[threadIdx.x] = sinf(a);
    }
    __syncthreads();
    int e = threadIdx.x;
    int bx = blockIdx.x;                    // bt*32 + x
    float U[KM], V[KM];
    #pragma unroll
    for (int k = 0; k < KM; k++) { U[k] = 0.f; V[k] = 0.f; }
    const float* hp = g_h + (size_t)bx * 32 * E + e;
    for (int y = 0; y < 32; y++) {
        float v = hp[(size_t)y * E];
        #pragma unroll
        for (int ky = 0; ky < KM; ky++) {
            int m = (y * ky) & 31;
            U[ky] += v * C[m];
            V[ky] -= v * S[m];
        }
    }
    float* up = g_U + (size_t)bx * KM * E + e;
    float* vp = g_V + (size_t)bx * KM * E + e;
    #pragma unroll
    for (int ky = 0; ky < KM; ky++) {
        up[(size_t)ky * E] = U[ky];
        vp[(size_t)ky * E] = V[ky];
    }
}

// ---------------- forward DFT stage 2 (over x) ----------------
__global__ void fwd_x_kernel() {
    __shared__ float C[32], S[32];
    if (threadIdx.x < 32) {
        float a = threadIdx.x * TWO_PI_32;
        C[threadIdx.x] = cosf(a); S[threadIdx.x] = sinf(a);
    }
    __syncthreads();
    int e  = threadIdx.x;
    int ky = blockIdx.x % KM;
    int bt = blockIdx.x / KM;
    int j0 = blockIdx.y * 12;
    float fr[12], fi[12];
    #pragma unroll
    for (int j = 0; j < 12; j++) { fr[j] = 0.f; fi[j] = 0.f; }
    const float* up = g_U + ((size_t)(bt * 32) * KM + ky) * E + e;
    const float* vp = g_V + ((size_t)(bt * 32) * KM + ky) * E + e;
    for (int x = 0; x < 32; x++) {
        float u = up[(size_t)x * KM * E];
        float v = vp[(size_t)x * KM * E];
        #pragma unroll
        for (int jj = 0; jj < 12; jj++) {
            int kx = j0 + jj + KX0;
            int m = (kx * x) & 31;
            float c = C[m], s = S[m];
            fr[jj] += u * c + v * s;
            fi[jj] += v * c - u * s;
        }
    }
    const float sc = 1.0f / 32.0f;
    #pragma unroll
    for (int jj = 0; jj < 12; jj++) {
        size_t idx = ((size_t)bt * NMODE + (size_t)(j0 + jj) * KM + ky) * E + e;
        g_fr[idx] = fr[jj] * sc;
        g_fi[idx] = fi[jj] * sc;
    }
}

// ---------------- block-diagonal complex MLP (4 mode-positions per block) ----------------
#define MPB 4
__global__ void bmlp_kernel(const float* __restrict__ w1, const float* __restrict__ b1,
                            const float* __restrict__ w2, const float* __restrict__ b2) {
    __shared__ float sfr[MPB][768], sfi[MPB][768];
    int t = threadIdx.x;
    size_t base = (size_t)blockIdx.x * MPB * E;
    #pragma unroll
    for (int m = 0; m < MPB; m++) {
        sfr[m][t] = g_fr[base + (size_t)m * E + t];
        sfi[m][t] = g_fi[base + (size_t)m * E + t];
    }
    __syncthreads();
    int n = t >> 6;

    const float* w0p = w1 + ((size_t)n * 64) * 64 + (t & 63);
    const float* w1p = w1 + ((size_t)(12 + n) * 64) * 64 + (t & 63);
    float ar[MPB], ai[MPB];
    float bre = b1[t], bim = b1[768 + t];
    #pragma unroll
    for (int m = 0; m < MPB; m++) { ar[m] = bre; ai[m] = bim; }
    #pragma unroll 8
    for (int i = 0; i < 64; i++) {
        float a  = w0p[(size_t)i * 64];
        float bb = w1p[(size_t)i * 64];
        #pragma unroll
        for (int m = 0; m < MPB; m++) {
            float fr = sfr[m][n * 64 + i], fi = sfi[m][n * 64 + i];
            ar[m] += fr * a - fi * bb;
            ai[m] += fi * a + fr * bb;
        }
    }
    __syncthreads();
    #pragma unroll
    for (int m = 0; m < MPB; m++) {
        sfr[m][t] = gelu_f(ar[m]);
        sfi[m][t] = gelu_f(ai[m]);
    }
    __syncthreads();

    const float* u0p = w2 + ((size_t)n * 64) * 64 + (t & 63);
    const float* u1p = w2 + ((size_t)(12 + n) * 64) * 64 + (t & 63);
    float cr[MPB], ci[MPB];
    float cre = b2[t], cim = b2[768 + t];
    #pragma unroll
    for (int m = 0; m < MPB; m++) { cr[m] = cre; ci[m] = cim; }
    #pragma unroll 8
    for (int i = 0; i < 64; i++) {
        float a  = u0p[(size_t)i * 64];
        float bb = u1p[(size_t)i * 64];
        #pragma unroll
        for (int m = 0; m < MPB; m++) {
            float orr = sfr[m][n * 64 + i], oii = sfi[m][n * 64 + i];
            cr[m] += orr * a - oii * bb;
            ci[m] += oii * a + orr * bb;
        }
    }
    #pragma unroll
    for (int m = 0; m < MPB; m++) {
        g_sr[base + (size_t)m * E + t] = softshrink_f(cr[m]);
        g_si[base + (size_t)m * E + t] = softshrink_f(ci[m]);
    }
}

// ---------------- inverse stage 1 (over kx) ----------------
__global__ void inv_x_kernel() {
    __shared__ float C[32], S[32];
    if (threadIdx.x < 32) {
        float a = threadIdx.x * TWO_PI_32;
        C[threadIdx.x] = cosf(a); S[threadIdx.x] = sinf(a);
    }
    __syncthreads();
    int e  = threadIdx.x;
    int bx = blockIdx.x;
    int ky = bx % KM;
    int x  = (bx / KM) % 32;
    int bt = bx / (32 * KM);
    float P = 0.f, Q = 0.f;
    const float* srp = g_sr + ((size_t)bt * NMODE + ky) * E + e;
    const float* sip = g_si + ((size_t)bt * NMODE + ky) * E + e;
    #pragma unroll 4
    for (int j = 0; j < J24; j++) {
        float sr = srp[(size_t)j * KM * E];
        float si = sip[(size_t)j * KM * E];
        int m = ((j + KX0) * x) & 31;
        float c = C[m], s = S[m];
        P += sr * c - si * s;
        Q += sr * s + si * c;
    }
    float wgt = (ky == 0 ? 1.0f : 2.0f) * (1.0f / 32.0f);
    size_t idx = ((size_t)(bt * 32 + x) * KM + ky) * E + e;
    g_P[idx] = P * wgt;
    g_Q[idx] = Q * wgt;
}

// ---------------- inverse stage 2 (over ky) + residual adds ----------------
__global__ void inv_y_kernel(const float* __restrict__ inp) {
    __shared__ float C[32], S[32];
    if (threadIdx.x < 32) {
        float a = threadIdx.x * TWO_PI_32;
        C[threadIdx.x] = cosf(a); S[threadIdx.x] = sinf(a);
    }
    __syncthreads();
    int e = threadIdx.x;
    int bx = blockIdx.x;                   // bt*32 + x
    float P[KM], Q[KM];
    const float* pp = g_P + (size_t)bx * KM * E + e;
    const float* qp = g_Q + (size_t)bx * KM * E + e;
    #pragma unroll
    for (int k = 0; k < KM; k++) {
        P[k] = pp[(size_t)k * E];
        Q[k] = qp[(size_t)k * E];
    }
    for (int y = 0; y < 32; y++) {
        float acc = 0.f;
        #pragma unroll
        for (int ky = 0; ky < KM; ky++) {
            int m = (ky * y) & 31;
            acc += P[ky] * C[m] - Q[ky] * S[m];
        }
        size_t idx = ((size_t)bx * 32 + y) * E + e;
        g_r1[idx] = acc + g_h[idx] + inp[idx];
    }
}

// ======================================================================
//  BF16 tensor-core GEMM (PROVEN in R12): 128x128 block tile, 8 warps,
//  warp tile 64x32, m16n8k16, BK=16, double-buffered packed-bf16x2 SMEM.
//  R14 delta: gemm1 writes bf16 mid; gemm2 reads bf16 A via raw uint4 copy.
// ======================================================================
#define BM 128
#define BN 128
#define BK 16
#define ASP 12      // As word stride per row
#define BSP 132     // Bp word stride per k-pair row

__device__ __forceinline__ void mma_bf16(float* c, const uint32_t* a, const uint32_t* b) {
    asm volatile(
        "mma.sync.aligned.m16n8k16.row.col.f32.bf16.bf16.f32 "
        "{%0,%1,%2,%3}, {%4,%5,%6,%7}, {%8,%9}, {%0,%1,%2,%3};\n"
        : "+f"(c[0]), "+f"(c[1]), "+f"(c[2]), "+f"(c[3])
        : "r"(a[0]), "r"(a[1]), "r"(a[2]), "r"(a[3]), "r"(b[0]), "r"(b[1]));
}

// ABF16: A is bf16 (k-contiguous, already packed) vs fp32 (convert at smem store)
// OBF16: write C as bf16 pairs vs fp32
template<int N_, bool GELU, bool RESID, bool ABF16, bool OBF16>
__device__ __forceinline__ void gemm_bf_core(const void* __restrict__ Av,
                                             const float* __restrict__ Bm,
                                             const float* __restrict__ bias,
                                             const float* __restrict__ res,
                                             void* __restrict__ CoutV, int K) {
    __shared__ uint32_t Asp[2][BM * ASP];
    __shared__ uint32_t Bps[2][8 * BSP];

    int t = threadIdx.x;
    int lane = t & 31, wid = t >> 5;
    int gid = lane >> 2, tig = lane & 3;
    int wm = (wid & 1) * 64;
    int wn = (wid >> 1) * 32;
    int m0 = blockIdx.y * BM, n0 = blockIdx.x * BN;

    float acc[4][4][4];
    #pragma unroll
    for (int i = 0; i < 4; i++)
        #pragma unroll
        for (int j = 0; j < 4; j++)
            #pragma unroll
            for (int k = 0; k < 4; k++) acc[i][j][k] = 0.f;

    // A loader mappings
    // fp32: 4 threads/row (ar=t>>2, 4 floats each -> 2 packed words)
    // bf16: 2 threads/row (ar2=t>>1, 8 bf16 each  -> 4 raw words)
    int ar  = t >> 2, ac  = (t & 3) * 4, acw = (t & 3) * 2;
    int ar2 = t >> 1, ach = (t & 1) * 8, acw2 = (t & 1) * 4;
    const float* Af = (const float*)Av;
    const __nv_bfloat16* Ah = (const __nv_bfloat16*)Av;
    const float* Ap0 = Af + (size_t)(m0 + ar) * K + ac;
    const float* Ap1 = Af + (size_t)(m0 + ar + 64) * K + ac;
    const __nv_bfloat16* Ah0 = Ah + (size_t)(m0 + ar2) * K + ach;
    // B loader: each thread packs one k-pair row over 4 n's
    int bp = t >> 5;
    int bc = (t & 31) * 4;
    const float* Bp0 = Bm + (size_t)(2 * bp) * N_ + n0 + bc;
    const float* Bp1 = Bp0 + N_;

    int NT = K / BK;

    // prologue: tile 0
    {
        uint32_t* As_ = Asp[0]; uint32_t* Bs_ = Bps[0];
        if (ABF16) {
            uint4 av = *(const uint4*)(Ah0);
            uint32_t* dst = &As_[ar2 * ASP + acw2];
            dst[0] = av.x; dst[1] = av.y; dst[2] = av.z; dst[3] = av.w;
        } else {
            float4 a0 = *(const float4*)(Ap0);
            float4 a1 = *(const float4*)(Ap1);
            As_[ar * ASP + acw]            = packbf2(a0.x, a0.y);
            As_[ar * ASP + acw + 1]        = packbf2(a0.z, a0.w);
            As_[(ar + 64) * ASP + acw]     = packbf2(a1.x, a1.y);
            As_[(ar + 64) * ASP + acw + 1] = packbf2(a1.z, a1.w);
        }
        float4 b0 = *(const float4*)(Bp0);
        float4 b1 = *(const float4*)(Bp1);
        Bs_[bp * BSP + bc + 0] = packbf2(b0.x, b1.x);
        Bs_[bp * BSP + bc + 1] = packbf2(b0.y, b1.y);
        Bs_[bp * BSP + bc + 2] = packbf2(b0.z, b1.z);
        Bs_[bp * BSP + bc + 3] = packbf2(b0.w, b1.w);
    }
    __syncthreads();

    for (int kt = 0; kt < NT; kt++) {
        float4 a0, a1, b0, b1;
        uint4 avh;
        bool has = (kt + 1) < NT;
        if (has) {
            int k0 = (kt + 1) * BK;
            if (ABF16) {
                avh = *(const uint4*)(Ah0 + k0);
            } else {
                a0 = *(const float4*)(Ap0 + k0);
                a1 = *(const float4*)(Ap1 + k0);
            }
            b0 = *(const float4*)(Bp0 + (size_t)k0 * N_);
            b1 = *(const float4*)(Bp1 + (size_t)k0 * N_);
        }

        const uint32_t* Asb = Asp[kt & 1];
        const uint32_t* Bsb = Bps[kt & 1];
        uint32_t af[4][4];
        #pragma unroll
        for (int ma = 0; ma < 4; ma++) {
            int r = wm + ma * 16 + gid;
            af[ma][0] = Asb[r * ASP + tig];
            af[ma][1] = Asb[(r + 8) * ASP + tig];
            af[ma][2] = Asb[r * ASP + tig + 4];
            af[ma][3] = Asb[(r + 8) * ASP + tig + 4];
        }
        uint32_t bf[4][2];
        #pragma unroll
        for (int na = 0; na < 4; na++) {
            int c = wn + na * 8 + gid;
            bf[na][0] = Bsb[tig * BSP + c];
            bf[na][1] = Bsb[(tig + 4) * BSP + c];
        }
        #pragma unroll
        for (int ma = 0; ma < 4; ma++)
            #pragma unroll
            for (int na = 0; na < 4; na++)
                mma_bf16(acc[ma][na], af[ma], bf[na]);

        if (has) {
            uint32_t* As_ = Asp[(kt + 1) & 1];
            uint32_t* Bs_ = Bps[(kt + 1) & 1];
            if (ABF16) {
                uint32_t* dst = &As_[ar2 * ASP + acw2];
                dst[0] = avh.x; dst[1] = avh.y; dst[2] = avh.z; dst[3] = avh.w;
            } else {
                As_[ar * ASP + acw]            = packbf2(a0.x, a0.y);
                As_[ar * ASP + acw + 1]        = packbf2(a0.z, a0.w);
                As_[(ar + 64) * ASP + acw]     = packbf2(a1.x, a1.y);
                As_[(ar + 64) * ASP + acw + 1] = packbf2(a1.z, a1.w);
            }
            Bs_[bp * BSP + bc + 0] = packbf2(b0.x, b1.x);
            Bs_[bp * BSP + bc + 1] = packbf2(b0.y, b1.y);
            Bs_[bp * BSP + bc + 2] = packbf2(b0.z, b1.z);
            Bs_[bp * BSP + bc + 3] = packbf2(b0.w, b1.w);
        }
        __syncthreads();
    }

    // epilogue (fp32 bias/activation/residual)
    #pragma unroll
    for (int ma = 0; ma < 4; ma++) {
        size_t r = m0 + wm + ma * 16 + gid;
        #pragma unroll
        for (int na = 0; na < 4; na++) {
            int c = n0 + wn + na * 8 + tig * 2;
            float v0 = acc[ma][na][0] + bias[c];
            float v1 = acc[ma][na][1] + bias[c + 1];
            float v2 = acc[ma][na][2] + bias[c];
            float v3 = acc[ma][na][3] + bias[c + 1];
            if (GELU) { v0 = gelu_f(v0); v1 = gelu_f(v1); v2 = gelu_f(v2); v3 = gelu_f(v3); }
            if (RESID) {
                float2 r0 = *(const float2*)(res + r * N_ + c);
                float2 r1 = *(const float2*)(res + (r + 8) * N_ + c);
                v0 += r0.x; v1 += r0.y; v2 += r1.x; v3 += r1.y;
            }
            if (OBF16) {
                __nv_bfloat16* Ch = (__nv_bfloat16*)CoutV;
                *(__nv_bfloat162*)(Ch + r * N_ + c)       = __floats2bfloat162_rn(v0, v1);
                *(__nv_bfloat162*)(Ch + (r + 8) * N_ + c) = __floats2bfloat162_rn(v2, v3);
            } else {
                float* Cf = (float*)CoutV;
                *(float2*)(Cf + r * N_ + c)       = make_float2(v0, v1);
                *(float2*)(Cf + (r + 8) * N_ + c) = make_float2(v2, v3);
            }
        }
    }
}

__global__ __launch_bounds__(256, 2) void gemm1_bf_kernel(const float* __restrict__ mw1,
                                                          const float* __restrict__ mb1) {
    gemm_bf_core<HID, true, false, false, true>(g_y, mw1, mb1, nullptr, (void*)g_midh, E);
}
__global__ __launch_bounds__(256, 2) void gemm2_bf_kernel(const float* __restrict__ mw2,
                                                          const float* __restrict__ mb2,
                                                          float* __restrict__ out) {
    gemm_bf_core<E, false, true, true, false>(g_midh, mw2, mb2, g_r1, (void*)out, HID);
}

// ---------------- launch ----------------
extern "C" void kernel_launch(void* const* d_in, const int* in_sizes, int n_in,
                              void* d_out, int out_size) {
    const float* inp  = (const float*)d_in[0];
    const float* w1   = (const float*)d_in[1];
    const float* b1   = (const float*)d_in[2];
    const float* w2   = (const float*)d_in[3];
    const float* b2   = (const float*)d_in[4];
    const float* ln1g = (const float*)d_in[5];
    const float* ln1b = (const float*)d_in[6];
    const float* ln2g = (const float*)d_in[7];
    const float* ln2b = (const float*)d_in[8];
    const float* mw1  = (const float*)d_in[9];
    const float* mb1  = (const float*)d_in[10];
    const float* mw2  = (const float*)d_in[11];
    const float* mb2  = (const float*)d_in[12];
    float* out = (float*)d_out;

    ln1_kernel<<<TOK, 256>>>(inp, ln1g, ln1b);
    fwd_y_kernel<<<BT * NXD, 768>>>();
    fwd_x_kernel<<<dim3(BT * KM, 2), 768>>>();
    bmlp_kernel<<<BT * NMODE / MPB, 768>>>(w1, b1, w2, b2);
    inv_x_kernel<<<BT * NXD * KM, 768>>>();
    inv_y_kernel<<<BT * NXD, 768>>>(inp);
    ln2_kernel<<<TOK, 256>>>(ln2g, ln2b);
    gemm1_bf_kernel<<<dim3(HID / BN, TOK / BM), 256>>>(mw1, mb1);
    gemm2_bf_kernel<<<dim3(E / BN, TOK / BM), 256>>>(mw2, mb2, out);
}

// round 17
// speedup vs baseline: 1.1549x; 1.0309x over previous
#include <cuda_runtime.h>
#include <cuda_bf16.h>
#include <math.h>
#include <stdint.h>

// Problem constants
#define BT   16          // B*T
#define E    768
#define NXD  32
#define NYD  32
#define NP   1024        // NX*NY
#define TOK  (BT*NP)     // 16384 tokens
#define KM   12          // kept y modes
#define J24  24          // kept x modes (kx = 5..28)
#define KX0  5
#define NMODE 288        // 24*12
#define HID  3072
#define TWO_PI_32 0.19634954084936207f

// ---------------- scratch (static device allocations; no cudaMalloc) ----------------
__device__ float g_h [TOK*E];          // LN1 output
__device__ float g_U [BT*NXD*KM*E];    // fwd y-DFT real
__device__ float g_V [BT*NXD*KM*E];    // fwd y-DFT imag
__device__ float g_fr[BT*NMODE*E];
__device__ float g_fi[BT*NMODE*E];
__device__ float g_sr[BT*NMODE*E];
__device__ float g_si[BT*NMODE*E];
__device__ float g_P [BT*NXD*KM*E];    // inv x-iDFT real (pre-weighted)
__device__ float g_Q [BT*NXD*KM*E];
__device__ float g_r1[TOK*E];          // spat + h + input  (res2)
__device__ float g_y [TOK*E];          // LN2 output
__device__ __nv_bfloat16 g_midh[(size_t)TOK*HID]; // gelu(y@mw1+mb1) (bf16)

__device__ __forceinline__ float gelu_f(float x) {
    return 0.5f * x * (1.0f + erff(x * 0.7071067811865475f));
}
__device__ __forceinline__ float softshrink_f(float x) {
    return x > 0.01f ? x - 0.01f : (x < -0.01f ? x + 0.01f : 0.0f);
}
__device__ __forceinline__ uint32_t packbf2(float lo, float hi) {
    __nv_bfloat162 p = __floats2bfloat162_rn(lo, hi);   // .x = lo (low 16 bits)
    return *reinterpret_cast<uint32_t*>(&p);
}

// ---------------- LayerNorm: ONE WARP PER TOKEN (no smem, no block sync) ----------------
// 256 threads/block = 8 tokens/block; each lane handles 24 channels as 6x float4.
__device__ __forceinline__ void ln_warp(const float* __restrict__ xr,
                                        const float* __restrict__ g,
                                        const float* __restrict__ b,
                                        float* __restrict__ orow, int lane) {
    float4 v[6];
    float s = 0.f, s2 = 0.f;
    #pragma unroll
    for (int c = 0; c < 6; c++) {
        v[c] = *(const float4*)(xr + c * 128 + lane * 4);
        s  += v[c].x + v[c].y + v[c].z + v[c].w;
        s2 += v[c].x*v[c].x + v[c].y*v[c].y + v[c].z*v[c].z + v[c].w*v[c].w;
    }
    #pragma unroll
    for (int o = 16; o > 0; o >>= 1) {
        s  += __shfl_xor_sync(0xffffffffu, s,  o);
        s2 += __shfl_xor_sync(0xffffffffu, s2, o);
    }
    float m = s * (1.0f / 768.0f);
    float r = rsqrtf(s2 * (1.0f / 768.0f) - m * m + 1e-5f);
    #pragma unroll
    for (int c = 0; c < 6; c++) {
        float4 gg = *(const float4*)(g + c * 128 + lane * 4);
        float4 bb = *(const float4*)(b + c * 128 + lane * 4);
        float4 o;
        o.x = (v[c].x - m) * r * gg.x + bb.x;
        o.y = (v[c].y - m) * r * gg.y + bb.y;
        o.z = (v[c].z - m) * r * gg.z + bb.z;
        o.w = (v[c].w - m) * r * gg.w + bb.w;
        *(float4*)(orow + c * 128 + lane * 4) = o;
    }
}

__global__ __launch_bounds__(256) void ln1_kernel(const float* __restrict__ x,
                                                  const float* __restrict__ g,
                                                  const float* __restrict__ b) {
    int tid = blockIdx.x * blockDim.x + threadIdx.x;
    size_t tok = tid >> 5;
    int lane = tid & 31;
    ln_warp(x + tok * E, g, b, g_h + tok * E, lane);
}
__global__ __launch_bounds__(256) void ln2_kernel(const float* __restrict__ g,
                                                  const float* __restrict__ b) {
    int tid = blockIdx.x * blockDim.x + threadIdx.x;
    size_t tok = tid >> 5;
    int lane = tid & 31;
    ln_warp(g_r1 + tok * E, g, b, g_y + tok * E, lane);
}

// ---------------- forward DFT stage 1 (over y): batch all 32 loads first ----------------
__global__ __launch_bounds__(768, 1) void fwd_y_kernel() {
    __shared__ float C[32], S[32];
    if (threadIdx.x < 32) {
        float a = threadIdx.x * TWO_PI_32;
        C[threadIdx.x] = cosf(a); S[threadIdx.x] = sinf(a);
    }
    __syncthreads();
    int e = threadIdx.x;
    int bx = blockIdx.x;                    // bt*32 + x
    const float* hp = g_h + (size_t)bx * 32 * E + e;
    float h[32];
    #pragma unroll
    for (int y = 0; y < 32; y++) h[y] = hp[(size_t)y * E];   // MLP=32

    float* up = g_U + (size_t)bx * KM * E + e;
    float* vp = g_V + (size_t)bx * KM * E + e;
    #pragma unroll
    for (int ky = 0; ky < KM; ky++) {
        float u = 0.f, v = 0.f;
        #pragma unroll
        for (int y = 0; y < 32; y++) {
            int m = (y * ky) & 31;
            u += h[y] * C[m];
            v -= h[y] * S[m];
        }
        up[(size_t)ky * E] = u;
        vp[(size_t)ky * E] = v;
    }
}

// ---------------- forward DFT stage 2 (over x): x-loads chunked by 8 ----------------
__global__ __launch_bounds__(768, 1) void fwd_x_kernel() {
    __shared__ float C[32], S[32];
    if (threadIdx.x < 32) {
        float a = threadIdx.x * TWO_PI_32;
        C[threadIdx.x] = cosf(a); S[threadIdx.x] = sinf(a);
    }
    __syncthreads();
    int e  = threadIdx.x;
    int ky = blockIdx.x % KM;
    int bt = blockIdx.x / KM;
    int j0 = blockIdx.y * 12;
    float fr[12], fi[12];
    #pragma unroll
    for (int j = 0; j < 12; j++) { fr[j] = 0.f; fi[j] = 0.f; }
    const float* up = g_U + ((size_t)(bt * 32) * KM + ky) * E + e;
    const float* vp = g_V + ((size_t)(bt * 32) * KM + ky) * E + e;
    #pragma unroll
    for (int x0 = 0; x0 < 32; x0 += 8) {
        float u[8], v[8];
        #pragma unroll
        for (int k = 0; k < 8; k++) {
            u[k] = up[(size_t)(x0 + k) * KM * E];
            v[k] = vp[(size_t)(x0 + k) * KM * E];
        }
        #pragma unroll
        for (int k = 0; k < 8; k++) {
            int x = x0 + k;
            #pragma unroll
            for (int jj = 0; jj < 12; jj++) {
                int kx = j0 + jj + KX0;
                int m = (kx * x) & 31;
                float c = C[m], s = S[m];
                fr[jj] += u[k] * c + v[k] * s;
                fi[jj] += v[k] * c - u[k] * s;
            }
        }
    }
    const float sc = 1.0f / 32.0f;
    #pragma unroll
    for (int jj = 0; jj < 12; jj++) {
        size_t idx = ((size_t)bt * NMODE + (size_t)(j0 + jj) * KM + ky) * E + e;
        g_fr[idx] = fr[jj] * sc;
        g_fi[idx] = fi[jj] * sc;
    }
}

// ---------------- block-diagonal complex MLP (4 mode-positions per block) ----------------
#define MPB 4
__global__ __launch_bounds__(768, 1) void bmlp_kernel(const float* __restrict__ w1,
                                                      const float* __restrict__ b1,
                                                      const float* __restrict__ w2,
                                                      const float* __restrict__ b2) {
    __shared__ float sfr[MPB][768], sfi[MPB][768];
    int t = threadIdx.x;
    size_t base = (size_t)blockIdx.x * MPB * E;
    #pragma unroll
    for (int m = 0; m < MPB; m++) {
        sfr[m][t] = g_fr[base + (size_t)m * E + t];
        sfi[m][t] = g_fi[base + (size_t)m * E + t];
    }
    __syncthreads();
    int n = t >> 6;

    const float* w0p = w1 + ((size_t)n * 64) * 64 + (t & 63);
    const float* w1p = w1 + ((size_t)(12 + n) * 64) * 64 + (t & 63);
    float ar[MPB], ai[MPB];
    float bre = b1[t], bim = b1[768 + t];
    #pragma unroll
    for (int m = 0; m < MPB; m++) { ar[m] = bre; ai[m] = bim; }
    #pragma unroll 8
    for (int i = 0; i < 64; i++) {
        float a  = w0p[(size_t)i * 64];
        float bb = w1p[(size_t)i * 64];
        #pragma unroll
        for (int m = 0; m < MPB; m++) {
            float fr = sfr[m][n * 64 + i], fi = sfi[m][n * 64 + i];
            ar[m] += fr * a - fi * bb;
            ai[m] += fi * a + fr * bb;
        }
    }
    __syncthreads();
    #pragma unroll
    for (int m = 0; m < MPB; m++) {
        sfr[m][t] = gelu_f(ar[m]);
        sfi[m][t] = gelu_f(ai[m]);
    }
    __syncthreads();

    const float* u0p = w2 + ((size_t)n * 64) * 64 + (t & 63);
    const float* u1p = w2 + ((size_t)(12 + n) * 64) * 64 + (t & 63);
    float cr[MPB], ci[MPB];
    float cre = b2[t], cim = b2[768 + t];
    #pragma unroll
    for (int m = 0; m < MPB; m++) { cr[m] = cre; ci[m] = cim; }
    #pragma unroll 8
    for (int i = 0; i < 64; i++) {
        float a  = u0p[(size_t)i * 64];
        float bb = u1p[(size_t)i * 64];
        #pragma unroll
        for (int m = 0; m < MPB; m++) {
            float orr = sfr[m][n * 64 + i], oii = sfi[m][n * 64 + i];
            cr[m] += orr * a - oii * bb;
            ci[m] += oii * a + orr * bb;
        }
    }
    #pragma unroll
    for (int m = 0; m < MPB; m++) {
        g_sr[base + (size_t)m * E + t] = softshrink_f(cr[m]);
        g_si[base + (size_t)m * E + t] = softshrink_f(ci[m]);
    }
}

// ---------------- inverse stage 1 (over kx): j-loads chunked by 8 ----------------
__global__ __launch_bounds__(768, 1) void inv_x_kernel() {
    __shared__ float C[32], S[32];
    if (threadIdx.x < 32) {
        float a = threadIdx.x * TWO_PI_32;
        C[threadIdx.x] = cosf(a); S[threadIdx.x] = sinf(a);
    }
    __syncthreads();
    int e  = threadIdx.x;
    int bx = blockIdx.x;
    int ky = bx % KM;
    int x  = (bx / KM) % 32;
    int bt = bx / (32 * KM);
    float P = 0.f, Q = 0.f;
    const float* srp = g_sr + ((size_t)bt * NMODE + ky) * E + e;
    const float* sip = g_si + ((size_t)bt * NMODE + ky) * E + e;
    #pragma unroll
    for (int j0 = 0; j0 < J24; j0 += 8) {
        float sr[8], si[8];
        #pragma unroll
        for (int k = 0; k < 8; k++) {
            sr[k] = srp[(size_t)(j0 + k) * KM * E];
            si[k] = sip[(size_t)(j0 + k) * KM * E];
        }
        #pragma unroll
        for (int k = 0; k < 8; k++) {
            int m = ((j0 + k + KX0) * x) & 31;
            float c = C[m], s = S[m];
            P += sr[k] * c - si[k] * s;
            Q += sr[k] * s + si[k] * c;
        }
    }
    float wgt = (ky == 0 ? 1.0f : 2.0f) * (1.0f / 32.0f);
    size_t idx = ((size_t)(bt * 32 + x) * KM + ky) * E + e;
    g_P[idx] = P * wgt;
    g_Q[idx] = Q * wgt;
}

// ---------------- inverse stage 2 (over ky) + residual adds: y chunked by 8 ----------------
__global__ __launch_bounds__(768, 1) void inv_y_kernel(const float* __restrict__ inp) {
    __shared__ float C[32], S[32];
    if (threadIdx.x < 32) {
        float a = threadIdx.x * TWO_PI_32;
        C[threadIdx.x] = cosf(a); S[threadIdx.x] = sinf(a);
    }
    __syncthreads();
    int e = threadIdx.x;
    int bx = blockIdx.x;                   // bt*32 + x
    float P[KM], Q[KM];
    const float* pp = g_P + (size_t)bx * KM * E + e;
    const float* qp = g_Q + (size_t)bx * KM * E + e;
    #pragma unroll
    for (int k = 0; k < KM; k++) {
        P[k] = pp[(size_t)k * E];
        Q[k] = qp[(size_t)k * E];
    }
    const float* hp = g_h + (size_t)bx * 32 * E + e;
    const float* ip = inp + (size_t)bx * 32 * E + e;
    float* rp = g_r1 + (size_t)bx * 32 * E + e;
    #pragma unroll
    for (int y0 = 0; y0 < 32; y0 += 8) {
        float hh[8], ii[8];
        #pragma unroll
        for (int k = 0; k < 8; k++) {
            hh[k] = hp[(size_t)(y0 + k) * E];
            ii[k] = ip[(size_t)(y0 + k) * E];
        }
        #pragma unroll
        for (int k = 0; k < 8; k++) {
            int y = y0 + k;
            float acc = 0.f;
            #pragma unroll
            for (int ky = 0; ky < KM; ky++) {
                int m = (ky * y) & 31;
                acc += P[ky] * C[m] - Q[ky] * S[m];
            }
            rp[(size_t)y * E] = acc + hh[k] + ii[k];
        }
    }
}

// ======================================================================
//  BF16 tensor-core GEMM (PROVEN R12/R14): 128x128 block tile, 8 warps,
//  warp tile 64x32, m16n8k16, BK=16, double-buffered packed-bf16x2 SMEM.
// ======================================================================
#define BM 128
#define BN 128
#define BK 16
#define ASP 12      // As word stride per row
#define BSP 132     // Bp word stride per k-pair row

__device__ __forceinline__ void mma_bf16(float* c, const uint32_t* a, const uint32_t* b) {
    asm volatile(
        "mma.sync.aligned.m16n8k16.row.col.f32.bf16.bf16.f32 "
        "{%0,%1,%2,%3}, {%4,%5,%6,%7}, {%8,%9}, {%0,%1,%2,%3};\n"
        : "+f"(c[0]), "+f"(c[1]), "+f"(c[2]), "+f"(c[3])
        : "r"(a[0]), "r"(a[1]), "r"(a[2]), "r"(a[3]), "r"(b[0]), "r"(b[1]));
}

// ABF16: A is bf16 (k-contiguous, already packed) vs fp32 (convert at smem store)
// OBF16: write C as bf16 pairs vs fp32
template<int N_, bool GELU, bool RESID, bool ABF16, bool OBF16>
__device__ __forceinline__ void gemm_bf_core(const void* __restrict__ Av,
                                             const float* __restrict__ Bm,
                                             const float* __restrict__ bias,
                                             const float* __restrict__ res,
                                             void* __restrict__ CoutV, int K) {
    __shared__ uint32_t Asp[2][BM * ASP];
    __shared__ uint32_t Bps[2][8 * BSP];

    int t = threadIdx.x;
    int lane = t & 31, wid = t >> 5;
    int gid = lane >> 2, tig = lane & 3;
    int wm = (wid & 1) * 64;
    int wn = (wid >> 1) * 32;
    int m0 = blockIdx.y * BM, n0 = blockIdx.x * BN;

    float acc[4][4][4];
    #pragma unroll
    for (int i = 0; i < 4; i++)
        #pragma unroll
        for (int j = 0; j < 4; j++)
            #pragma unroll
            for (int k = 0; k < 4; k++) acc[i][j][k] = 0.f;

    int ar  = t >> 2, ac  = (t & 3) * 4, acw = (t & 3) * 2;
    int ar2 = t >> 1, ach = (t & 1) * 8, acw2 = (t & 1) * 4;
    const float* Af = (const float*)Av;
    const __nv_bfloat16* Ah = (const __nv_bfloat16*)Av;
    const float* Ap0 = Af + (size_t)(m0 + ar) * K + ac;
    const float* Ap1 = Af + (size_t)(m0 + ar + 64) * K + ac;
    const __nv_bfloat16* Ah0 = Ah + (size_t)(m0 + ar2) * K + ach;
    int bp = t >> 5;
    int bc = (t & 31) * 4;
    const float* Bp0 = Bm + (size_t)(2 * bp) * N_ + n0 + bc;
    const float* Bp1 = Bp0 + N_;

    int NT = K / BK;

    {
        uint32_t* As_ = Asp[0]; uint32_t* Bs_ = Bps[0];
        if (ABF16) {
            uint4 av = *(const uint4*)(Ah0);
            uint32_t* dst = &As_[ar2 * ASP + acw2];
            dst[0] = av.x; dst[1] = av.y; dst[2] = av.z; dst[3] = av.w;
        } else {
            float4 a0 = *(const float4*)(Ap0);
            float4 a1 = *(const float4*)(Ap1);
            As_[ar * ASP + acw]            = packbf2(a0.x, a0.y);
            As_[ar * ASP + acw + 1]        = packbf2(a0.z, a0.w);
            As_[(ar + 64) * ASP + acw]     = packbf2(a1.x, a1.y);
            As_[(ar + 64) * ASP + acw + 1] = packbf2(a1.z, a1.w);
        }
        float4 b0 = *(const float4*)(Bp0);
        float4 b1 = *(const float4*)(Bp1);
        Bs_[bp * BSP + bc + 0] = packbf2(b0.x, b1.x);
        Bs_[bp * BSP + bc + 1] = packbf2(b0.y, b1.y);
        Bs_[bp * BSP + bc + 2] = packbf2(b0.z, b1.z);
        Bs_[bp * BSP + bc + 3] = packbf2(b0.w, b1.w);
    }
    __syncthreads();

    for (int kt = 0; kt < NT; kt++) {
        float4 a0, a1, b0, b1;
        uint4 avh;
        bool has = (kt + 1) < NT;
        if (has) {
            int k0 = (kt + 1) * BK;
            if (ABF16) {
                avh = *(const uint4*)(Ah0 + k0);
            } else {
                a0 = *(const float4*)(Ap0 + k0);
                a1 = *(const float4*)(Ap1 + k0);
            }
            b0 = *(const float4*)(Bp0 + (size_t)k0 * N_);
            b1 = *(const float4*)(Bp1 + (size_t)k0 * N_);
        }

        const uint32_t* Asb = Asp[kt & 1];
        const uint32_t* Bsb = Bps[kt & 1];
        uint32_t af[4][4];
        #pragma unroll
        for (int ma = 0; ma < 4; ma++) {
            int r = wm + ma * 16 + gid;
            af[ma][0] = Asb[r * ASP + tig];
            af[ma][1] = Asb[(r + 8) * ASP + tig];
            af[ma][2] = Asb[r * ASP + tig + 4];
            af[ma][3] = Asb[(r + 8) * ASP + tig + 4];
        }
        uint32_t bf[4][2];
        #pragma unroll
        for (int na = 0; na < 4; na++) {
            int c = wn + na * 8 + gid;
            bf[na][0] = Bsb[tig * BSP + c];
            bf[na][1] = Bsb[(tig + 4) * BSP + c];
        }
        #pragma unroll
        for (int ma = 0; ma < 4; ma++)
            #pragma unroll
            for (int na = 0; na < 4; na++)
                mma_bf16(acc[ma][na], af[ma], bf[na]);

        if (has) {
            uint32_t* As_ = Asp[(kt + 1) & 1];
            uint32_t* Bs_ = Bps[(kt + 1) & 1];
            if (ABF16) {
                uint32_t* dst = &As_[ar2 * ASP + acw2];
                dst[0] = avh.x; dst[1] = avh.y; dst[2] = avh.z; dst[3] = avh.w;
            } else {
                As_[ar * ASP + acw]            = packbf2(a0.x, a0.y);
                As_[ar * ASP + acw + 1]        = packbf2(a0.z, a0.w);
                As_[(ar + 64) * ASP + acw]     = packbf2(a1.x, a1.y);
                As_[(ar + 64) * ASP + acw + 1] = packbf2(a1.z, a1.w);
            }
            Bs_[bp * BSP + bc + 0] = packbf2(b0.x, b1.x);
            Bs_[bp * BSP + bc + 1] = packbf2(b0.y, b1.y);
            Bs_[bp * BSP + bc + 2] = packbf2(b0.z, b1.z);
            Bs_[bp * BSP + bc + 3] = packbf2(b0.w, b1.w);
        }
        __syncthreads();
    }

    #pragma unroll
    for (int ma = 0; ma < 4; ma++) {
        size_t r = m0 + wm + ma * 16 + gid;
        #pragma unroll
        for (int na = 0; na < 4; na++) {
            int c = n0 + wn + na * 8 + tig * 2;
            float v0 = acc[ma][na][0] + bias[c];
            float v1 = acc[ma][na][1] + bias[c + 1];
            float v2 = acc[ma][na][2] + bias[c];
            float v3 = acc[ma][na][3] + bias[c + 1];
            if (GELU) { v0 = gelu_f(v0); v1 = gelu_f(v1); v2 = gelu_f(v2); v3 = gelu_f(v3); }
            if (RESID) {
                float2 r0 = *(const float2*)(res + r * N_ + c);
                float2 r1 = *(const float2*)(res + (r + 8) * N_ + c);
                v0 += r0.x; v1 += r0.y; v2 += r1.x; v3 += r1.y;
            }
            if (OBF16) {
                __nv_bfloat16* Ch = (__nv_bfloat16*)CoutV;
                *(__nv_bfloat162*)(Ch + r * N_ + c)       = __floats2bfloat162_rn(v0, v1);
                *(__nv_bfloat162*)(Ch + (r + 8) * N_ + c) = __floats2bfloat162_rn(v2, v3);
            } else {
                float* Cf = (float*)CoutV;
                *(float2*)(Cf + r * N_ + c)       = make_float2(v0, v1);
                *(float2*)(Cf + (r + 8) * N_ + c) = make_float2(v2, v3);
            }
        }
    }
}

__global__ __launch_bounds__(256, 2) void gemm1_bf_kernel(const float* __restrict__ mw1,
                                                          const float* __restrict__ mb1) {
    gemm_bf_core<HID, true, false, false, true>(g_y, mw1, mb1, nullptr, (void*)g_midh, E);
}
__global__ __launch_bounds__(256, 2) void gemm2_bf_kernel(const float* __restrict__ mw2,
                                                          const float* __restrict__ mb2,
                                                          float* __restrict__ out) {
    gemm_bf_core<E, false, true, true, false>(g_midh, mw2, mb2, g_r1, (void*)out, HID);
}

// ---------------- launch ----------------
extern "C" void kernel_launch(void* const* d_in, const int* in_sizes, int n_in,
                              void* d_out, int out_size) {
    const float* inp  = (const float*)d_in[0];
    const float* w1   = (const float*)d_in[1];
    const float* b1   = (const float*)d_in[2];
    const float* w2   = (const float*)d_in[3];
    const float* b2   = (const float*)d_in[4];
    const float* ln1g = (const float*)d_in[5];
    const float* ln1b = (const float*)d_in[6];
    const float* ln2g = (const float*)d_in[7];
    const float* ln2b = (const float*)d_in[8];
    const float* mw1  = (const float*)d_in[9];
    const float* mb1  = (const float*)d_in[10];
    const float* mw2  = (const float*)d_in[11];
    const float* mb2  = (const float*)d_in[12];
    float* out = (float*)d_out;

    ln1_kernel<<<TOK / 8, 256>>>(inp, ln1g, ln1b);
    fwd_y_kernel<<<BT * NXD, 768>>>();
    fwd_x_kernel<<<dim3(BT * KM, 2), 768>>>();
    bmlp_kernel<<<BT * NMODE / MPB, 768>>>(w1, b1, w2, b2);
    inv_x_kernel<<<BT * NXD * KM, 768>>>();
    inv_y_kernel<<<BT * NXD, 768>>>(inp);
    ln2_kernel<<<TOK / 8, 256>>>(ln2g, ln2b);
    gemm1_bf_kernel<<<dim3(HID / BN, TOK / BM), 256>>>(mw1, mb1);
    gemm2_bf_kernel<<<dim3(E / BN, TOK / BM), 256>>>(mw2, mb2, out);
}